// round 10
// baseline (speedup 1.0000x reference)
#include <cuda_runtime.h>
#include <cuda_bf16.h>
#include <cstdint>

// ----------------------------------------------------------------------------
// GCN: 5x (GCNConv + ReLU) + global mean pool + linear head.
//   Fixed shapes: N=100000, E=1600000, H=128, C=10, L=5, G=64
//   - CSR build over dst (self-loops included), norm = dis[s]*dis[d]
//   - Per layer: ONE fused kernel k_layer:
//       phase A: block aggregates its 128 dst rows (warp-per-row CSR gather),
//                16-row smem chunks, split to tf32-hi/bf16-lo mma fragments
//       phase B: relu(agg @ W + b) via m16n8k8 tf32 mma, 3-term compensated.
//     2 blocks/SM -> one block's tensor mainloop overlaps the other's gather.
//   - All layers' W fragments pre-split in ONE upfront kernel.
//   - Chunked mean-pool (sorted batch -> per-chunk partial sums + atomics)
// ----------------------------------------------------------------------------

#define MAXN 100352
#define MAXT 1703936      // >= E + N
#define MAXG 1024
#define MAXL 8
#define HH   128

__device__ int   g_cnt[MAXN];
__device__ float g_dis[MAXN];
__device__ int   g_rowptr[MAXN + 1];
__device__ int   g_cursor[MAXN];
__device__ int2  g_edges[MAXT];
__device__ float g_x1 [(size_t)MAXN * HH];
__device__ float g_x2 [(size_t)MAXN * HH];
__device__ int   g_bsum[256];
__device__ int   g_gstart[MAXG + 1];
__device__ float g_psum[(size_t)MAXG * HH];
__device__ uint2    g_wh[MAXL * 8192];   // W tf32-hi fragments (all layers)
__device__ uint32_t g_wl[MAXL * 8192];   // W bf16-lo fragments

// ------------------------------- graph prep ---------------------------------
__global__ void k_init(int* cnt, int n) {
    int i = blockIdx.x * blockDim.x + threadIdx.x;
    if (i < n) cnt[i] = 1;  // self loop
}

__global__ void k_count(const int* __restrict__ dst, int* cnt, int e) {
    int i = blockIdx.x * blockDim.x + threadIdx.x;
    if (i < e) atomicAdd(&cnt[dst[i]], 1);
}

// partial block sums for exclusive scan; also emits dis = rsqrt(cnt)
__global__ void k_scan1(const int* __restrict__ cnt, int* bsum, float* dis, int n) {
    __shared__ int sh[256];
    int t = threadIdx.x;
    int base = blockIdx.x * 1024 + t * 4;
    int s = 0;
#pragma unroll
    for (int i = 0; i < 4; i++)
        if (base + i < n) {
            int c = cnt[base + i];
            s += c;
            dis[base + i] = rsqrtf((float)c);   // cnt >= 1 always
        }
    sh[t] = s;
    __syncthreads();
#pragma unroll
    for (int off = 128; off > 0; off >>= 1) {
        if (t < off) sh[t] += sh[t + off];
        __syncthreads();
    }
    if (t == 0) bsum[blockIdx.x] = sh[0];
}

__global__ void k_scan2(int* bsum, int* rowptr, int nb, int n) {
    __shared__ int sh[256];
    int t = threadIdx.x;
    sh[t] = (t < nb) ? bsum[t] : 0;
    __syncthreads();
    for (int off = 1; off < 256; off <<= 1) {
        int v = (t >= off) ? sh[t - off] : 0;
        __syncthreads();
        sh[t] += v;
        __syncthreads();
    }
    if (t < nb) bsum[t] = (t == 0) ? 0 : sh[t - 1];
    if (t == 0) rowptr[n] = sh[nb - 1];
}

__global__ void k_scan3(const int* __restrict__ cnt, const int* __restrict__ bsumex,
                        int* rowptr, int* cursor, int n) {
    __shared__ int sh[256];
    int t = threadIdx.x;
    int base = blockIdx.x * 1024 + t * 4;
    int v0 = 0, v1 = 0, v2 = 0, v3 = 0;
    if (base + 0 < n) v0 = cnt[base + 0];
    if (base + 1 < n) v1 = cnt[base + 1];
    if (base + 2 < n) v2 = cnt[base + 2];
    if (base + 3 < n) v3 = cnt[base + 3];
    int s = v0 + v1 + v2 + v3;
    sh[t] = s;
    __syncthreads();
    for (int off = 1; off < 256; off <<= 1) {
        int v = (t >= off) ? sh[t - off] : 0;
        __syncthreads();
        sh[t] += v;
        __syncthreads();
    }
    int ex = (t == 0) ? 0 : sh[t - 1];
    int off0 = bsumex[blockIdx.x] + ex;
    if (base + 0 < n) { rowptr[base + 0] = off0;                cursor[base + 0] = off0; }
    if (base + 1 < n) { rowptr[base + 1] = off0 + v0;           cursor[base + 1] = off0 + v0; }
    if (base + 2 < n) { rowptr[base + 2] = off0 + v0 + v1;      cursor[base + 2] = off0 + v0 + v1; }
    if (base + 3 < n) { rowptr[base + 3] = off0 + v0 + v1 + v2; cursor[base + 3] = off0 + v0 + v1 + v2; }
}

__global__ void k_fill(const int* __restrict__ src, const int* __restrict__ dst,
                       const float* __restrict__ dis, int* cursor, int2* edges,
                       int e, int n) {
    int i = blockIdx.x * blockDim.x + threadIdx.x;
    if (i >= e + n) return;
    int s, d;
    if (i < e) { s = src[i]; d = dst[i]; }
    else       { s = d = i - e; }
    float w = dis[s] * dis[d];
    int pos = atomicAdd(&cursor[d], 1);
    edges[pos] = make_int2(s, __float_as_int(w));
}

// ------------------------- tensor-core GEMM helpers --------------------------
__device__ __forceinline__ uint32_t f2tf32(float v) {
    uint32_t u;
    asm("cvt.rna.tf32.f32 %0, %1;" : "=r"(u) : "f"(v));
    return u;
}
// pack two residuals as bf16x2; e0 -> lower half, e1 -> upper half
__device__ __forceinline__ uint32_t packbf(float e0, float e1) {
    uint32_t r;
    asm("cvt.rn.bf16x2.f32 %0, %1, %2;" : "=r"(r) : "f"(e1), "f"(e0));
    return r;
}
__device__ __forceinline__ void mma8(float* c,
                                     uint32_t a0, uint32_t a1, uint32_t a2, uint32_t a3,
                                     uint32_t b0, uint32_t b1) {
    asm volatile(
        "mma.sync.aligned.m16n8k8.row.col.f32.tf32.tf32.f32 "
        "{%0,%1,%2,%3}, {%4,%5,%6,%7}, {%8,%9}, {%0,%1,%2,%3};"
        : "+f"(c[0]), "+f"(c[1]), "+f"(c[2]), "+f"(c[3])
        : "r"(a0), "r"(a1), "r"(a2), "r"(a3), "r"(b0), "r"(b1));
}

// ----------------- per-layer W fragment pre-split (ALL layers) ---------------
__global__ void k_prepw_all(const float* __restrict__ Ws, uint2* __restrict__ wh,
                            uint32_t* __restrict__ wl) {
    int l = blockIdx.x >> 5;
    int idx = (blockIdx.x & 31) * 256 + threadIdx.x;   // 0..8191
    const float* W = Ws + (size_t)l * HH * HH;
    int lane = idx & 31, tile = idx >> 5;
    int nt = tile & 15, ks = tile >> 4;
    int t = lane & 3, g = lane >> 2;
    int row = ks * 8 + t, col = nt * 8 + g;
    float v0 = W[row * HH + col];
    float v1 = W[(row + 4) * HH + col];
    uint32_t h0 = f2tf32(v0), h1 = f2tf32(v1);
    float l0 = v0 - __uint_as_float(h0), l1 = v1 - __uint_as_float(h1);
    wh[l * 8192 + idx] = make_uint2(h0, h1);
    wl[l * 8192 + idx] = packbf(l0, l1);
}

// --------------------------- fused SpMM + GEMM layer -------------------------
// Block owns 128 dst rows. Phase A: CSR-gather aggregate each row (warp-per-row,
// identical order to the old k_spmm), stage 16-row chunks in smem (stride 132,
// conflict-free), split to fragments. Phase B: tf32+bf16 3-term mma + bias +
// relu + store. Smem: Ah 64KB + Al 32KB + raw 8.25KB = 104.25KB -> 2 blocks/SM.
#define SMEM_LAYER (98304 + 16 * 132 * 4)

__global__ __launch_bounds__(256, 2)
void k_layer(const int* __restrict__ rowptr, const int2* __restrict__ edges,
             const float* __restrict__ xin,
             const uint2* __restrict__ wh, const uint32_t* __restrict__ wl,
             const float* __restrict__ bias, float* __restrict__ out, int n) {
    extern __shared__ char sh[];
    uint4*  Ah  = (uint4*)sh;                    // 4096 slots (64KB)
    uint2*  Al  = (uint2*)(sh + 65536);          // 4096 slots (32KB)
    float*  raw = (float*)(sh + 98304);          // [16][132]

    const int tid  = threadIdx.x;
    const int lane = tid & 31;
    const int warp = tid >> 5;
    const int m0 = blockIdx.x << 7;
    const float4* x4 = (const float4*)xin;

    // ================= Phase A: aggregate + fragment-split =================
#pragma unroll 1
    for (int c = 0; c < 8; c++) {
#pragma unroll
        for (int rr = 0; rr < 2; rr++) {
            int lrow = warp * 2 + rr;            // 0..15 within chunk
            int row  = m0 + c * 16 + lrow;
            float4 acc = make_float4(0.f, 0.f, 0.f, 0.f);
            if (row < n) {
                int s = rowptr[row], e = rowptr[row + 1];
                int j = s;
                for (; j + 4 <= e; j += 4) {
                    int2 e0 = __ldg(&edges[j + 0]);
                    int2 e1 = __ldg(&edges[j + 1]);
                    int2 e2 = __ldg(&edges[j + 2]);
                    int2 e3 = __ldg(&edges[j + 3]);
                    float4 v0 = __ldg(&x4[(size_t)e0.x * 32 + lane]);
                    float4 v1 = __ldg(&x4[(size_t)e1.x * 32 + lane]);
                    float4 v2 = __ldg(&x4[(size_t)e2.x * 32 + lane]);
                    float4 v3 = __ldg(&x4[(size_t)e3.x * 32 + lane]);
                    float w0 = __int_as_float(e0.y), w1 = __int_as_float(e1.y);
                    float w2 = __int_as_float(e2.y), w3 = __int_as_float(e3.y);
                    acc.x += w0 * v0.x; acc.y += w0 * v0.y; acc.z += w0 * v0.z; acc.w += w0 * v0.w;
                    acc.x += w1 * v1.x; acc.y += w1 * v1.y; acc.z += w1 * v1.z; acc.w += w1 * v1.w;
                    acc.x += w2 * v2.x; acc.y += w2 * v2.y; acc.z += w2 * v2.z; acc.w += w2 * v2.w;
                    acc.x += w3 * v3.x; acc.y += w3 * v3.y; acc.z += w3 * v3.z; acc.w += w3 * v3.w;
                }
                for (; j < e; j++) {
                    int2 ed = __ldg(&edges[j]);
                    float w = __int_as_float(ed.y);
                    float4 v = __ldg(&x4[(size_t)ed.x * 32 + lane]);
                    acc.x += w * v.x; acc.y += w * v.y; acc.z += w * v.z; acc.w += w * v.w;
                }
            }
            *(float4*)&raw[lrow * 132 + lane * 4] = acc;
        }
        __syncthreads();
        // split this 16-row chunk into mma fragments (mt group = c)
#pragma unroll
        for (int s2 = tid; s2 < 512; s2 += 256) {
            int ks = s2 >> 5, ln = s2 & 31;
            int g = ln >> 2, t = ln & 3;
            int col = ks * 8 + t;
            float v0 = raw[g * 132 + col];
            float v1 = raw[(g + 8) * 132 + col];
            float v2 = raw[g * 132 + col + 4];
            float v3 = raw[(g + 8) * 132 + col + 4];
            uint32_t h0 = f2tf32(v0), h1 = f2tf32(v1), h2 = f2tf32(v2), h3 = f2tf32(v3);
            float l0 = v0 - __uint_as_float(h0), l1 = v1 - __uint_as_float(h1);
            float l2 = v2 - __uint_as_float(h2), l3 = v3 - __uint_as_float(h3);
            Ah[(ks * 8 + c) * 32 + ln] = make_uint4(h0, h1, h2, h3);
            Al[(ks * 8 + c) * 32 + ln] = make_uint2(packbf(l0, l1), packbf(l2, l3));
        }
        __syncthreads();
    }

    // ======================= Phase B: mma mainloop =========================
    const int g = lane >> 2, t = lane & 3;
    const int wm = warp >> 2;      // 0..1  (64 rows each)
    const int wn = warp & 3;       // 0..3  (32 cols each)

    float acc[4][4][4];
#pragma unroll
    for (int a = 0; a < 4; a++)
#pragma unroll
        for (int b = 0; b < 4; b++)
#pragma unroll
            for (int cc = 0; cc < 4; cc++) acc[a][b][cc] = 0.f;

#pragma unroll 2
    for (int ks = 0; ks < 16; ks++) {
        uint2 bh[4]; uint32_t blp[4];
#pragma unroll
        for (int nt = 0; nt < 4; nt++) {
            int slot = (ks * 16 + wn * 4 + nt) * 32 + lane;
            bh[nt]  = __ldg(&wh[slot]);
            blp[nt] = __ldg(&wl[slot]);
        }
        uint4 ah[4]; uint2 alp[4];
#pragma unroll
        for (int mt = 0; mt < 4; mt++) {
            int slot = (ks * 8 + wm * 4 + mt) * 32 + lane;
            ah[mt]  = Ah[slot];
            alp[mt] = Al[slot];
        }
#pragma unroll
        for (int mt = 0; mt < 4; mt++) {
            uint32_t a0 = ah[mt].x, a1 = ah[mt].y, a2 = ah[mt].z, a3 = ah[mt].w;
            uint32_t q0 = alp[mt].x << 16, q1 = alp[mt].x & 0xFFFF0000u;
            uint32_t q2 = alp[mt].y << 16, q3 = alp[mt].y & 0xFFFF0000u;
#pragma unroll
            for (int nt = 0; nt < 4; nt++) {
                uint32_t b0 = bh[nt].x, b1 = bh[nt].y;
                uint32_t r0 = blp[nt] << 16, r1 = blp[nt] & 0xFFFF0000u;
                mma8(acc[mt][nt], a0, a1, a2, a3, b0, b1);   // hi*hi
                mma8(acc[mt][nt], a0, a1, a2, a3, r0, r1);   // hi*lo
                mma8(acc[mt][nt], q0, q1, q2, q3, b0, b1);   // lo*hi
            }
        }
    }

    // ---- epilogue: bias + relu + store ----
#pragma unroll
    for (int nt = 0; nt < 4; nt++) {
        int c = wn * 32 + nt * 8 + 2 * t;
        float b0 = __ldg(&bias[c]), b1 = __ldg(&bias[c + 1]);
#pragma unroll
        for (int mt = 0; mt < 4; mt++) {
            int m = m0 + wm * 64 + mt * 16 + g;
            if (m < n) {
                float2 o = make_float2(fmaxf(acc[mt][nt][0] + b0, 0.f),
                                       fmaxf(acc[mt][nt][1] + b1, 0.f));
                *(float2*)&out[(size_t)m * HH + c] = o;
            }
            if (m + 8 < n) {
                float2 o = make_float2(fmaxf(acc[mt][nt][2] + b0, 0.f),
                                       fmaxf(acc[mt][nt][3] + b1, 0.f));
                *(float2*)&out[(size_t)(m + 8) * HH + c] = o;
            }
        }
    }
}

// ------------------------------ pooling / head ------------------------------
__global__ void k_gbz(const int* __restrict__ batch, int* gstart, float* psum,
                      int n, int g_num) {
    int i = blockIdx.x * blockDim.x + threadIdx.x;
    if (i < g_num * HH) psum[i] = 0.f;
    if (i <= g_num) {
        int lo = 0, hi = n;
        while (lo < hi) {
            int mid = (lo + hi) >> 1;
            if (batch[mid] < i) lo = mid + 1; else hi = mid;
        }
        gstart[i] = lo;
    }
}

// chunked per-graph partial sums: block = 256-row chunk, thread = column
__global__ __launch_bounds__(128)
void k_psum(const float* __restrict__ x, const int* __restrict__ batch,
            float* __restrict__ psum, int n) {
    __shared__ int bsh[256];
    const int t = threadIdx.x;            // column 0..127
    const int r0 = blockIdx.x * 256;
    const int len = min(256, n - r0);
    for (int i = t; i < len; i += 128) bsh[i] = batch[r0 + i];
    __syncthreads();

    if (bsh[0] == bsh[len - 1]) {
        float acc = 0.f;
        int i = 0;
        for (; i + 8 <= len; i += 8) {
            float v0 = x[(size_t)(r0 + i + 0) * HH + t];
            float v1 = x[(size_t)(r0 + i + 1) * HH + t];
            float v2 = x[(size_t)(r0 + i + 2) * HH + t];
            float v3 = x[(size_t)(r0 + i + 3) * HH + t];
            float v4 = x[(size_t)(r0 + i + 4) * HH + t];
            float v5 = x[(size_t)(r0 + i + 5) * HH + t];
            float v6 = x[(size_t)(r0 + i + 6) * HH + t];
            float v7 = x[(size_t)(r0 + i + 7) * HH + t];
            acc += ((v0 + v1) + (v2 + v3)) + ((v4 + v5) + (v6 + v7));
        }
        for (; i < len; i++) acc += x[(size_t)(r0 + i) * HH + t];
        atomicAdd(&psum[(size_t)bsh[0] * HH + t], acc);
    } else {
        float acc = 0.f;
        int curg = bsh[0];
        int i = 0;
        for (; i + 4 <= len; i += 4) {
            float v0 = x[(size_t)(r0 + i + 0) * HH + t];
            float v1 = x[(size_t)(r0 + i + 1) * HH + t];
            float v2 = x[(size_t)(r0 + i + 2) * HH + t];
            float v3 = x[(size_t)(r0 + i + 3) * HH + t];
            int g0 = bsh[i], g1 = bsh[i + 1], g2 = bsh[i + 2], g3 = bsh[i + 3];
            if (g0 != curg) { atomicAdd(&psum[(size_t)curg * HH + t], acc); acc = 0.f; curg = g0; }
            acc += v0;
            if (g1 != curg) { atomicAdd(&psum[(size_t)curg * HH + t], acc); acc = 0.f; curg = g1; }
            acc += v1;
            if (g2 != curg) { atomicAdd(&psum[(size_t)curg * HH + t], acc); acc = 0.f; curg = g2; }
            acc += v2;
            if (g3 != curg) { atomicAdd(&psum[(size_t)curg * HH + t], acc); acc = 0.f; curg = g3; }
            acc += v3;
        }
        for (; i < len; i++) {
            int g = bsh[i];
            if (g != curg) { atomicAdd(&psum[(size_t)curg * HH + t], acc); acc = 0.f; curg = g; }
            acc += x[(size_t)(r0 + i) * HH + t];
        }
        atomicAdd(&psum[(size_t)curg * HH + t], acc);
    }
}

// head: pooled = psum/cnt ; out = pooled @ W_out + b_out
__global__ void k_out(const float* __restrict__ psum, const int* __restrict__ gstart,
                      const float* __restrict__ Wout, const float* __restrict__ bout,
                      float* __restrict__ out, int C) {
    __shared__ float pr[HH];
    int g = blockIdx.x, t = threadIdx.x;
    float cntf = (float)(gstart[g + 1] - gstart[g]);
    float inv = 1.0f / fmaxf(cntf, 1.0f);
    pr[t] = psum[(size_t)g * HH + t] * inv;
    __syncthreads();
    if (t < C) {
        float s = bout[t];
#pragma unroll 8
        for (int k = 0; k < HH; k++) s += pr[k] * Wout[k * C + t];
        out[g * C + t] = s;
    }
}

// --------------------------------- launch -----------------------------------
extern "C" void kernel_launch(void* const* d_in, const int* in_sizes, int n_in,
                              void* d_out, int out_size) {
    const float* x     = (const float*)d_in[0];
    const int*   ei    = (const int*)d_in[1];
    const int*   batch = (const int*)d_in[2];
    int iw, ibs, iwo, ibo;
    if (n_in >= 8) { iw = 4; ibs = 5; iwo = 6; ibo = 7; }  // num_graphs at index 3
    else           { iw = 3; ibs = 4; iwo = 5; ibo = 6; }
    const float* Ws   = (const float*)d_in[iw];
    const float* bs   = (const float*)d_in[ibs];
    const float* Wout = (const float*)d_in[iwo];
    const float* bout = (const float*)d_in[ibo];

    int N = in_sizes[2];
    int E = in_sizes[1] / 2;
    int H = in_sizes[0] / N;            // expect 128
    int C = in_sizes[ibo];
    int L = in_sizes[ibs] / H;
    int G = out_size / C;
    if (N > MAXN || (E + N) > MAXT || G > MAXG || H != HH || L > MAXL) return;

    void* p;
    cudaGetSymbolAddress(&p, g_cnt);     int*   cnt    = (int*)p;
    cudaGetSymbolAddress(&p, g_dis);     float* dis    = (float*)p;
    cudaGetSymbolAddress(&p, g_rowptr);  int*   rowptr = (int*)p;
    cudaGetSymbolAddress(&p, g_cursor);  int*   cursor = (int*)p;
    cudaGetSymbolAddress(&p, g_edges);   int2*  edges  = (int2*)p;
    cudaGetSymbolAddress(&p, g_x1);      float* x1     = (float*)p;
    cudaGetSymbolAddress(&p, g_x2);      float* x2     = (float*)p;
    cudaGetSymbolAddress(&p, g_bsum);    int*   bsum   = (int*)p;
    cudaGetSymbolAddress(&p, g_gstart);  int*   gstart = (int*)p;
    cudaGetSymbolAddress(&p, g_psum);    float* psum   = (float*)p;
    cudaGetSymbolAddress(&p, g_wh);      uint2* wh     = (uint2*)p;
    cudaGetSymbolAddress(&p, g_wl);      uint32_t* wl  = (uint32_t*)p;

    cudaFuncSetAttribute(k_layer, cudaFuncAttributeMaxDynamicSharedMemorySize, SMEM_LAYER);

    const int* src = ei;
    const int* dst = ei + E;

    // W fragment pre-split for all layers (off the per-layer critical path)
    k_prepw_all<<<32 * L, 256>>>(Ws, wh, wl);
    // graph boundaries + zero pooled accumulator (independent of layers)
    k_gbz<<<(G * HH + 255) / 256, 256>>>(batch, gstart, psum, N, G);

    k_init <<<(N + 255) / 256, 256>>>(cnt, N);
    k_count<<<(E + 255) / 256, 256>>>(dst, cnt, E);

    int NB = (N + 1023) / 1024;
    k_scan1<<<NB, 256>>>(cnt, bsum, dis, N);
    k_scan2<<<1, 256>>>(bsum, rowptr, NB, N);
    k_scan3<<<NB, 256>>>(cnt, bsum, rowptr, cursor, N);
    k_fill <<<(E + N + 255) / 256, 256>>>(src, dst, dis, cursor, edges, E, N);

    const float* xin = x;
    for (int l = 0; l < L; l++) {
        float* xout = (l & 1) ? x2 : x1;
        k_layer<<<(N + 127) / 128, 256, SMEM_LAYER>>>(rowptr, edges, xin,
                                                      wh + (size_t)l * 8192,
                                                      wl + (size_t)l * 8192,
                                                      bs + (size_t)l * H, xout, N);
        xin = xout;
    }

    k_psum<<<(N + 255) / 256, 128>>>(xin, batch, psum, N);
    k_out <<<G, HH>>>(psum, gstart, Wout, bout, (float*)d_out, C);
}

// round 11
// speedup vs baseline: 1.4044x; 1.4044x over previous
#include <cuda_runtime.h>
#include <cuda_bf16.h>
#include <cstdint>

// ----------------------------------------------------------------------------
// GCN: 5x (GCNConv + ReLU) + global mean pool + linear head.
//   Fixed shapes: N=100000, E=1600000, H=128, C=10, L=5, G=64
//   - CSR build over dst (self-loops included), norm = dis[s]*dis[d]
//   - Per layer: agg = A_norm * x   (warp-per-row CSR SpMM, no atomics,
//                high occupancy for L2 latency hiding -- keep SEPARATE from GEMM)
//                x   = relu(agg @ W + b)  via tensor-core tf32 mma with
//                3-term error-compensated split (hi=tf32, lo=bf16).
//   - All layers' W fragments pre-split in ONE upfront kernel.
//   - Chunked mean-pool (sorted batch -> per-chunk partial sums + atomics)
// ----------------------------------------------------------------------------

#define MAXN 100352
#define MAXT 1703936      // >= E + N
#define MAXG 1024
#define MAXL 8
#define HH   128

__device__ int   g_cnt[MAXN];
__device__ float g_dis[MAXN];
__device__ int   g_rowptr[MAXN + 1];
__device__ int   g_cursor[MAXN];
__device__ int2  g_edges[MAXT];
__device__ float g_agg[(size_t)MAXN * HH];
__device__ float g_x1 [(size_t)MAXN * HH];
__device__ float g_x2 [(size_t)MAXN * HH];
__device__ int   g_bsum[256];
__device__ int   g_gstart[MAXG + 1];
__device__ float g_psum[(size_t)MAXG * HH];
__device__ uint2    g_wh[MAXL * 8192];   // W tf32-hi fragments (all layers)
__device__ uint32_t g_wl[MAXL * 8192];   // W bf16-lo fragments

// ------------------------------- graph prep ---------------------------------
__global__ void k_count(const int* __restrict__ dst, int* cnt, int e) {
    int i = blockIdx.x * blockDim.x + threadIdx.x;
    if (i < e) atomicAdd(&cnt[dst[i]], 1);
}

// partial block sums for exclusive scan; also emits dis = rsqrt(cnt)
__global__ void k_scan1(const int* __restrict__ cnt, int* bsum, float* dis, int n) {
    __shared__ int sh[256];
    int t = threadIdx.x;
    int base = blockIdx.x * 1024 + t * 4;
    int s = 0;
#pragma unroll
    for (int i = 0; i < 4; i++)
        if (base + i < n) {
            int c = cnt[base + i];
            s += c;
            dis[base + i] = rsqrtf((float)c);   // cnt >= 1 always (self loop)
        }
    sh[t] = s;
    __syncthreads();
#pragma unroll
    for (int off = 128; off > 0; off >>= 1) {
        if (t < off) sh[t] += sh[t + off];
        __syncthreads();
    }
    if (t == 0) bsum[blockIdx.x] = sh[0];
}

__global__ void k_scan2(int* bsum, int* rowptr, int nb, int n) {
    __shared__ int sh[256];
    int t = threadIdx.x;
    sh[t] = (t < nb) ? bsum[t] : 0;
    __syncthreads();
    for (int off = 1; off < 256; off <<= 1) {
        int v = (t >= off) ? sh[t - off] : 0;
        __syncthreads();
        sh[t] += v;
        __syncthreads();
    }
    if (t < nb) bsum[t] = (t == 0) ? 0 : sh[t - 1];
    if (t == 0) rowptr[n] = sh[nb - 1];
}

__global__ void k_scan3(const int* __restrict__ cnt, const int* __restrict__ bsumex,
                        int* rowptr, int* cursor, int n) {
    __shared__ int sh[256];
    int t = threadIdx.x;
    int base = blockIdx.x * 1024 + t * 4;
    int v0 = 0, v1 = 0, v2 = 0, v3 = 0;
    if (base + 0 < n) v0 = cnt[base + 0];
    if (base + 1 < n) v1 = cnt[base + 1];
    if (base + 2 < n) v2 = cnt[base + 2];
    if (base + 3 < n) v3 = cnt[base + 3];
    int s = v0 + v1 + v2 + v3;
    sh[t] = s;
    __syncthreads();
    for (int off = 1; off < 256; off <<= 1) {
        int v = (t >= off) ? sh[t - off] : 0;
        __syncthreads();
        sh[t] += v;
        __syncthreads();
    }
    int ex = (t == 0) ? 0 : sh[t - 1];
    int off0 = bsumex[blockIdx.x] + ex;
    if (base + 0 < n) { rowptr[base + 0] = off0;                cursor[base + 0] = off0; }
    if (base + 1 < n) { rowptr[base + 1] = off0 + v0;           cursor[base + 1] = off0 + v0; }
    if (base + 2 < n) { rowptr[base + 2] = off0 + v0 + v1;      cursor[base + 2] = off0 + v0 + v1; }
    if (base + 3 < n) { rowptr[base + 3] = off0 + v0 + v1 + v2; cursor[base + 3] = off0 + v0 + v1 + v2; }
}

__global__ void k_fill(const int* __restrict__ src, const int* __restrict__ dst,
                       const float* __restrict__ dis, int* cursor, int2* edges,
                       int e, int n) {
    int i = blockIdx.x * blockDim.x + threadIdx.x;
    if (i >= e + n) return;
    int s, d;
    if (i < e) { s = src[i]; d = dst[i]; }
    else       { s = d = i - e; }
    float w = dis[s] * dis[d];
    int pos = atomicAdd(&cursor[d], 1);
    edges[pos] = make_int2(s, __float_as_int(w));
}

// --------------------------------- SpMM -------------------------------------
// warp per destination row; deep unroll (16 loads in flight) for L2 latency.
// Accumulation order identical to prior rounds (sequential j into one acc).
__global__ void k_spmm(const int* __restrict__ rowptr, const int2* __restrict__ edges,
                       const float* __restrict__ xin, float* __restrict__ xout, int n) {
    int row  = (blockIdx.x * blockDim.x + threadIdx.x) >> 5;
    int lane = threadIdx.x & 31;
    if (row >= n) return;
    int s = rowptr[row], e = rowptr[row + 1];
    const float4* x4 = (const float4*)xin;
    float4 acc = make_float4(0.f, 0.f, 0.f, 0.f);
    int j = s;
    for (; j + 8 <= e; j += 8) {
        int2 e0 = __ldg(&edges[j + 0]);
        int2 e1 = __ldg(&edges[j + 1]);
        int2 e2 = __ldg(&edges[j + 2]);
        int2 e3 = __ldg(&edges[j + 3]);
        int2 e4 = __ldg(&edges[j + 4]);
        int2 e5 = __ldg(&edges[j + 5]);
        int2 e6 = __ldg(&edges[j + 6]);
        int2 e7 = __ldg(&edges[j + 7]);
        float4 v0 = __ldg(&x4[(size_t)e0.x * 32 + lane]);
        float4 v1 = __ldg(&x4[(size_t)e1.x * 32 + lane]);
        float4 v2 = __ldg(&x4[(size_t)e2.x * 32 + lane]);
        float4 v3 = __ldg(&x4[(size_t)e3.x * 32 + lane]);
        float4 v4 = __ldg(&x4[(size_t)e4.x * 32 + lane]);
        float4 v5 = __ldg(&x4[(size_t)e5.x * 32 + lane]);
        float4 v6 = __ldg(&x4[(size_t)e6.x * 32 + lane]);
        float4 v7 = __ldg(&x4[(size_t)e7.x * 32 + lane]);
        float w0 = __int_as_float(e0.y), w1 = __int_as_float(e1.y);
        float w2 = __int_as_float(e2.y), w3 = __int_as_float(e3.y);
        float w4 = __int_as_float(e4.y), w5 = __int_as_float(e5.y);
        float w6 = __int_as_float(e6.y), w7 = __int_as_float(e7.y);
        acc.x += w0 * v0.x; acc.y += w0 * v0.y; acc.z += w0 * v0.z; acc.w += w0 * v0.w;
        acc.x += w1 * v1.x; acc.y += w1 * v1.y; acc.z += w1 * v1.z; acc.w += w1 * v1.w;
        acc.x += w2 * v2.x; acc.y += w2 * v2.y; acc.z += w2 * v2.z; acc.w += w2 * v2.w;
        acc.x += w3 * v3.x; acc.y += w3 * v3.y; acc.z += w3 * v3.z; acc.w += w3 * v3.w;
        acc.x += w4 * v4.x; acc.y += w4 * v4.y; acc.z += w4 * v4.z; acc.w += w4 * v4.w;
        acc.x += w5 * v5.x; acc.y += w5 * v5.y; acc.z += w5 * v5.z; acc.w += w5 * v5.w;
        acc.x += w6 * v6.x; acc.y += w6 * v6.y; acc.z += w6 * v6.z; acc.w += w6 * v6.w;
        acc.x += w7 * v7.x; acc.y += w7 * v7.y; acc.z += w7 * v7.z; acc.w += w7 * v7.w;
    }
    for (; j < e; j++) {
        int2 ed = __ldg(&edges[j]);
        float w = __int_as_float(ed.y);
        float4 v = __ldg(&x4[(size_t)ed.x * 32 + lane]);
        acc.x += w * v.x; acc.y += w * v.y; acc.z += w * v.z; acc.w += w * v.w;
    }
    ((float4*)xout)[(size_t)row * 32 + lane] = acc;
}

// ------------------------- tensor-core GEMM helpers --------------------------
__device__ __forceinline__ uint32_t f2tf32(float v) {
    uint32_t u;
    asm("cvt.rna.tf32.f32 %0, %1;" : "=r"(u) : "f"(v));
    return u;
}
// pack two residuals as bf16x2; e0 -> lower half, e1 -> upper half
__device__ __forceinline__ uint32_t packbf(float e0, float e1) {
    uint32_t r;
    asm("cvt.rn.bf16x2.f32 %0, %1, %2;" : "=r"(r) : "f"(e1), "f"(e0));
    return r;
}
__device__ __forceinline__ void mma8(float* c,
                                     uint32_t a0, uint32_t a1, uint32_t a2, uint32_t a3,
                                     uint32_t b0, uint32_t b1) {
    asm volatile(
        "mma.sync.aligned.m16n8k8.row.col.f32.tf32.tf32.f32 "
        "{%0,%1,%2,%3}, {%4,%5,%6,%7}, {%8,%9}, {%0,%1,%2,%3};"
        : "+f"(c[0]), "+f"(c[1]), "+f"(c[2]), "+f"(c[3])
        : "r"(a0), "r"(a1), "r"(a2), "r"(a3), "r"(b0), "r"(b1));
}

// ----------------- per-layer W fragment pre-split (ALL layers) ---------------
__global__ void k_prepw_all(const float* __restrict__ Ws, uint2* __restrict__ wh,
                            uint32_t* __restrict__ wl) {
    int l = blockIdx.x >> 5;
    int idx = (blockIdx.x & 31) * 256 + threadIdx.x;   // 0..8191
    const float* W = Ws + (size_t)l * HH * HH;
    int lane = idx & 31, tile = idx >> 5;
    int nt = tile & 15, ks = tile >> 4;
    int t = lane & 3, g = lane >> 2;
    int row = ks * 8 + t, col = nt * 8 + g;
    float v0 = W[row * HH + col];
    float v1 = W[(row + 4) * HH + col];
    uint32_t h0 = f2tf32(v0), h1 = f2tf32(v1);
    float l0 = v0 - __uint_as_float(h0), l1 = v1 - __uint_as_float(h1);
    wh[l * 8192 + idx] = make_uint2(h0, h1);
    wl[l * 8192 + idx] = packbf(l0, l1);
}

// --------------------------------- GEMM --------------------------------------
// out[m][c] = relu( sum_k A[m][k]*W[k][c] + bias[c] ), block tile 128x128, K=128
// Shared holds ONLY the A fragments (96KB) -> 2 blocks/SM. W fragments come
// from the pre-split global arrays (coalesced LDG.64/LDG.32).
#define SMEM_GEMM 98304

__global__ __launch_bounds__(256)
void k_gemm_tc(const float* __restrict__ A,
               const uint2* __restrict__ wh, const uint32_t* __restrict__ wl,
               const float* __restrict__ bias, float* __restrict__ out, int n) {
    extern __shared__ char sh[];
    uint4* Ah = (uint4*)sh;                      // 4096 slots
    uint2* Al = (uint2*)(sh + 65536);            // 4096 slots

    const int tid  = threadIdx.x;
    const int lane = tid & 31;
    const int g = lane >> 2, t = lane & 3;
    const int m0 = blockIdx.x << 7;

    // ---- stage A fragments (each thread owns whole lane-slots -> vector STS) ----
#pragma unroll
    for (int i = 0; i < 16; i++) {
        int s    = tid + i * 256;      // slot id; (s & 31) == lane
        int tile = s >> 5;             // 0..127
        int mt = tile & 7, ks = tile >> 3;
        int mrow = m0 + mt * 16 + g;
        int col  = ks * 8 + t;
        float v0 = 0.f, v1 = 0.f, v2 = 0.f, v3 = 0.f;
        if (mrow < n) {
            v0 = __ldg(&A[(size_t)mrow * HH + col]);
            v2 = __ldg(&A[(size_t)mrow * HH + col + 4]);
        }
        if (mrow + 8 < n) {
            v1 = __ldg(&A[(size_t)(mrow + 8) * HH + col]);
            v3 = __ldg(&A[(size_t)(mrow + 8) * HH + col + 4]);
        }
        uint32_t h0 = f2tf32(v0), h1 = f2tf32(v1), h2 = f2tf32(v2), h3 = f2tf32(v3);
        float l0 = v0 - __uint_as_float(h0), l1 = v1 - __uint_as_float(h1);
        float l2 = v2 - __uint_as_float(h2), l3 = v3 - __uint_as_float(h3);
        Ah[s] = make_uint4(h0, h1, h2, h3);
        Al[s] = make_uint2(packbf(l0, l1), packbf(l2, l3));
    }
    __syncthreads();

    const int warp = tid >> 5;
    const int wm = warp >> 2;      // 0..1  (64 rows each)
    const int wn = warp & 3;       // 0..3  (32 cols each)

    float acc[4][4][4];
#pragma unroll
    for (int a = 0; a < 4; a++)
#pragma unroll
        for (int b = 0; b < 4; b++)
#pragma unroll
            for (int c = 0; c < 4; c++) acc[a][b][c] = 0.f;

#pragma unroll 2
    for (int ks = 0; ks < 16; ks++) {
        uint2 bh[4]; uint32_t blp[4];
#pragma unroll
        for (int nt = 0; nt < 4; nt++) {
            int slot = (ks * 16 + wn * 4 + nt) * 32 + lane;
            bh[nt]  = __ldg(&wh[slot]);
            blp[nt] = __ldg(&wl[slot]);
        }
        uint4 ah[4]; uint2 alp[4];
#pragma unroll
        for (int mt = 0; mt < 4; mt++) {
            int slot = (ks * 8 + wm * 4 + mt) * 32 + lane;
            ah[mt]  = Ah[slot];
            alp[mt] = Al[slot];
        }
#pragma unroll
        for (int mt = 0; mt < 4; mt++) {
            uint32_t a0 = ah[mt].x, a1 = ah[mt].y, a2 = ah[mt].z, a3 = ah[mt].w;
            uint32_t q0 = alp[mt].x << 16, q1 = alp[mt].x & 0xFFFF0000u;
            uint32_t q2 = alp[mt].y << 16, q3 = alp[mt].y & 0xFFFF0000u;
#pragma unroll
            for (int nt = 0; nt < 4; nt++) {
                uint32_t b0 = bh[nt].x, b1 = bh[nt].y;
                uint32_t r0 = blp[nt] << 16, r1 = blp[nt] & 0xFFFF0000u;
                mma8(acc[mt][nt], a0, a1, a2, a3, b0, b1);   // hi*hi
                mma8(acc[mt][nt], a0, a1, a2, a3, r0, r1);   // hi*lo
                mma8(acc[mt][nt], q0, q1, q2, q3, b0, b1);   // lo*hi
            }
        }
    }

    // ---- epilogue: bias + relu + store ----
#pragma unroll
    for (int nt = 0; nt < 4; nt++) {
        int c = wn * 32 + nt * 8 + 2 * t;
        float b0 = __ldg(&bias[c]), b1 = __ldg(&bias[c + 1]);
#pragma unroll
        for (int mt = 0; mt < 4; mt++) {
            int m = m0 + wm * 64 + mt * 16 + g;
            if (m < n) {
                float2 o = make_float2(fmaxf(acc[mt][nt][0] + b0, 0.f),
                                       fmaxf(acc[mt][nt][1] + b1, 0.f));
                *(float2*)&out[(size_t)m * HH + c] = o;
            }
            if (m + 8 < n) {
                float2 o = make_float2(fmaxf(acc[mt][nt][2] + b0, 0.f),
                                       fmaxf(acc[mt][nt][3] + b1, 0.f));
                *(float2*)&out[(size_t)(m + 8) * HH + c] = o;
            }
        }
    }
}

// ------------------------------ pooling / head ------------------------------
// graph boundaries + zero pooled accumulator + init cnt=1 (self loop)
__global__ void k_gbz(const int* __restrict__ batch, int* gstart, float* psum,
                      int* cnt, int n, int g_num) {
    int i = blockIdx.x * blockDim.x + threadIdx.x;
    if (i < n) cnt[i] = 1;                 // self loop seed for k_count
    if (i < g_num * HH) psum[i] = 0.f;
    if (i <= g_num) {
        int lo = 0, hi = n;
        while (lo < hi) {
            int mid = (lo + hi) >> 1;
            if (batch[mid] < i) lo = mid + 1; else hi = mid;
        }
        gstart[i] = lo;
    }
}

// chunked per-graph partial sums: block = 256-row chunk, thread = column
__global__ __launch_bounds__(128)
void k_psum(const float* __restrict__ x, const int* __restrict__ batch,
            float* __restrict__ psum, int n) {
    __shared__ int bsh[256];
    const int t = threadIdx.x;            // column 0..127
    const int r0 = blockIdx.x * 256;
    const int len = min(256, n - r0);
    for (int i = t; i < len; i += 128) bsh[i] = batch[r0 + i];
    __syncthreads();

    if (bsh[0] == bsh[len - 1]) {
        float acc = 0.f;
        int i = 0;
        for (; i + 8 <= len; i += 8) {
            float v0 = x[(size_t)(r0 + i + 0) * HH + t];
            float v1 = x[(size_t)(r0 + i + 1) * HH + t];
            float v2 = x[(size_t)(r0 + i + 2) * HH + t];
            float v3 = x[(size_t)(r0 + i + 3) * HH + t];
            float v4 = x[(size_t)(r0 + i + 4) * HH + t];
            float v5 = x[(size_t)(r0 + i + 5) * HH + t];
            float v6 = x[(size_t)(r0 + i + 6) * HH + t];
            float v7 = x[(size_t)(r0 + i + 7) * HH + t];
            acc += ((v0 + v1) + (v2 + v3)) + ((v4 + v5) + (v6 + v7));
        }
        for (; i < len; i++) acc += x[(size_t)(r0 + i) * HH + t];
        atomicAdd(&psum[(size_t)bsh[0] * HH + t], acc);
    } else {
        float acc = 0.f;
        int curg = bsh[0];
        int i = 0;
        for (; i + 4 <= len; i += 4) {
            float v0 = x[(size_t)(r0 + i + 0) * HH + t];
            float v1 = x[(size_t)(r0 + i + 1) * HH + t];
            float v2 = x[(size_t)(r0 + i + 2) * HH + t];
            float v3 = x[(size_t)(r0 + i + 3) * HH + t];
            int g0 = bsh[i], g1 = bsh[i + 1], g2 = bsh[i + 2], g3 = bsh[i + 3];
            if (g0 != curg) { atomicAdd(&psum[(size_t)curg * HH + t], acc); acc = 0.f; curg = g0; }
            acc += v0;
            if (g1 != curg) { atomicAdd(&psum[(size_t)curg * HH + t], acc); acc = 0.f; curg = g1; }
            acc += v1;
            if (g2 != curg) { atomicAdd(&psum[(size_t)curg * HH + t], acc); acc = 0.f; curg = g2; }
            acc += v2;
            if (g3 != curg) { atomicAdd(&psum[(size_t)curg * HH + t], acc); acc = 0.f; curg = g3; }
            acc += v3;
        }
        for (; i < len; i++) {
            int g = bsh[i];
            if (g != curg) { atomicAdd(&psum[(size_t)curg * HH + t], acc); acc = 0.f; curg = g; }
            acc += x[(size_t)(r0 + i) * HH + t];
        }
        atomicAdd(&psum[(size_t)curg * HH + t], acc);
    }
}

// head: pooled = psum/cnt ; out = pooled @ W_out + b_out
__global__ void k_out(const float* __restrict__ psum, const int* __restrict__ gstart,
                      const float* __restrict__ Wout, const float* __restrict__ bout,
                      float* __restrict__ out, int C) {
    __shared__ float pr[HH];
    int g = blockIdx.x, t = threadIdx.x;
    float cntf = (float)(gstart[g + 1] - gstart[g]);
    float inv = 1.0f / fmaxf(cntf, 1.0f);
    pr[t] = psum[(size_t)g * HH + t] * inv;
    __syncthreads();
    if (t < C) {
        float s = bout[t];
#pragma unroll 8
        for (int k = 0; k < HH; k++) s += pr[k] * Wout[k * C + t];
        out[g * C + t] = s;
    }
}

// --------------------------------- launch -----------------------------------
extern "C" void kernel_launch(void* const* d_in, const int* in_sizes, int n_in,
                              void* d_out, int out_size) {
    const float* x     = (const float*)d_in[0];
    const int*   ei    = (const int*)d_in[1];
    const int*   batch = (const int*)d_in[2];
    int iw, ibs, iwo, ibo;
    if (n_in >= 8) { iw = 4; ibs = 5; iwo = 6; ibo = 7; }  // num_graphs at index 3
    else           { iw = 3; ibs = 4; iwo = 5; ibo = 6; }
    const float* Ws   = (const float*)d_in[iw];
    const float* bs   = (const float*)d_in[ibs];
    const float* Wout = (const float*)d_in[iwo];
    const float* bout = (const float*)d_in[ibo];

    int N = in_sizes[2];
    int E = in_sizes[1] / 2;
    int H = in_sizes[0] / N;            // expect 128
    int C = in_sizes[ibo];
    int L = in_sizes[ibs] / H;
    int G = out_size / C;
    if (N > MAXN || (E + N) > MAXT || G > MAXG || H != HH || L > MAXL) return;

    void* p;
    cudaGetSymbolAddress(&p, g_cnt);     int*   cnt    = (int*)p;
    cudaGetSymbolAddress(&p, g_dis);     float* dis    = (float*)p;
    cudaGetSymbolAddress(&p, g_rowptr);  int*   rowptr = (int*)p;
    cudaGetSymbolAddress(&p, g_cursor);  int*   cursor = (int*)p;
    cudaGetSymbolAddress(&p, g_edges);   int2*  edges  = (int2*)p;
    cudaGetSymbolAddress(&p, g_agg);     float* agg    = (float*)p;
    cudaGetSymbolAddress(&p, g_x1);      float* x1     = (float*)p;
    cudaGetSymbolAddress(&p, g_x2);      float* x2     = (float*)p;
    cudaGetSymbolAddress(&p, g_bsum);    int*   bsum   = (int*)p;
    cudaGetSymbolAddress(&p, g_gstart);  int*   gstart = (int*)p;
    cudaGetSymbolAddress(&p, g_psum);    float* psum   = (float*)p;
    cudaGetSymbolAddress(&p, g_wh);      uint2* wh     = (uint2*)p;
    cudaGetSymbolAddress(&p, g_wl);      uint32_t* wl  = (uint32_t*)p;

    cudaFuncSetAttribute(k_gemm_tc, cudaFuncAttributeMaxDynamicSharedMemorySize, SMEM_GEMM);

    const int* src = ei;
    const int* dst = ei + E;

    // init cnt=1 / graph boundaries / zero pooled accumulator (one pass)
    k_gbz<<<(N + 255) / 256, 256>>>(batch, gstart, psum, cnt, N, G);
    // W fragment pre-split for all layers (off the per-layer critical path)
    k_prepw_all<<<32 * L, 256>>>(Ws, wh, wl);

    k_count<<<(E + 255) / 256, 256>>>(dst, cnt, E);

    int NB = (N + 1023) / 1024;
    k_scan1<<<NB, 256>>>(cnt, bsum, dis, N);
    k_scan2<<<1, 256>>>(bsum, rowptr, NB, N);
    k_scan3<<<NB, 256>>>(cnt, bsum, rowptr, cursor, N);
    k_fill <<<(E + N + 255) / 256, 256>>>(src, dst, dis, cursor, edges, E, N);

    const float* xin = x;
    for (int l = 0; l < L; l++) {
        k_spmm<<<(N + 7) / 8, 256>>>(rowptr, edges, xin, agg, N);
        float* xout = (l & 1) ? x2 : x1;
        k_gemm_tc<<<(N + 127) / 128, 256, SMEM_GEMM>>>(agg, wh + (size_t)l * 8192,
                                                       wl + (size_t)l * 8192,
                                                       bs + (size_t)l * H, xout, N);
        xin = xout;
    }

    k_psum<<<(N + 255) / 256, 128>>>(xin, batch, psum, N);
    k_out <<<G, HH>>>(psum, gstart, Wout, bout, (float*)d_out, C);
}

// round 12
// speedup vs baseline: 1.5568x; 1.1085x over previous
#include <cuda_runtime.h>
#include <cuda_bf16.h>
#include <cuda_fp16.h>
#include <cstdint>

// ----------------------------------------------------------------------------
// GCN: 5x (GCNConv + ReLU) + global mean pool + linear head.
//   Fixed shapes: N=100000, E=1600000, H=128, C=10, L=5, G=64
//   - CSR build over dst (self-loops included), norm = dis[s]*dis[d]
//   - Layer 1: fp32 gather SpMM (signed input -> keep full precision)
//   - Layers 2..L: fp16 gather SpMM (post-ReLU activations stored as fp16:
//     non-negative -> cancellation-free aggregation, halved L2 traffic)
//   - GEMM: tf32 mma with 3-term compensated split (hi=tf32, lo=bf16),
//     fp32 accumulate; epilogue emits fp16 activations.
//   - Chunked mean-pool (sorted batch) reads fp16.
// ----------------------------------------------------------------------------

#define MAXN 100352
#define MAXT 1703936      // >= E + N
#define MAXG 1024
#define MAXL 8
#define HH   128

__device__ int    g_cnt[MAXN];
__device__ float  g_dis[MAXN];
__device__ int    g_rowptr[MAXN + 1];
__device__ int    g_cursor[MAXN];
__device__ int2   g_edges[MAXT];
__device__ float  g_agg[(size_t)MAXN * HH];
__device__ __half g_xh1[(size_t)MAXN * HH];
__device__ __half g_xh2[(size_t)MAXN * HH];
__device__ int    g_bsum[256];
__device__ int    g_gstart[MAXG + 1];
__device__ float  g_psum[(size_t)MAXG * HH];
__device__ uint2    g_wh[MAXL * 8192];   // W tf32-hi fragments (all layers)
__device__ uint32_t g_wl[MAXL * 8192];   // W bf16-lo fragments

// ------------------------------- graph prep ---------------------------------
__global__ void k_count(const int* __restrict__ dst, int* cnt, int e) {
    int i = blockIdx.x * blockDim.x + threadIdx.x;
    if (i < e) atomicAdd(&cnt[dst[i]], 1);
}

// partial block sums for exclusive scan; also emits dis = rsqrt(cnt)
__global__ void k_scan1(const int* __restrict__ cnt, int* bsum, float* dis, int n) {
    __shared__ int sh[256];
    int t = threadIdx.x;
    int base = blockIdx.x * 1024 + t * 4;
    int s = 0;
#pragma unroll
    for (int i = 0; i < 4; i++)
        if (base + i < n) {
            int c = cnt[base + i];
            s += c;
            dis[base + i] = rsqrtf((float)c);   // cnt >= 1 always (self loop)
        }
    sh[t] = s;
    __syncthreads();
#pragma unroll
    for (int off = 128; off > 0; off >>= 1) {
        if (t < off) sh[t] += sh[t + off];
        __syncthreads();
    }
    if (t == 0) bsum[blockIdx.x] = sh[0];
}

__global__ void k_scan2(int* bsum, int* rowptr, int nb, int n) {
    __shared__ int sh[256];
    int t = threadIdx.x;
    sh[t] = (t < nb) ? bsum[t] : 0;
    __syncthreads();
    for (int off = 1; off < 256; off <<= 1) {
        int v = (t >= off) ? sh[t - off] : 0;
        __syncthreads();
        sh[t] += v;
        __syncthreads();
    }
    if (t < nb) bsum[t] = (t == 0) ? 0 : sh[t - 1];
    if (t == 0) rowptr[n] = sh[nb - 1];
}

__global__ void k_scan3(const int* __restrict__ cnt, const int* __restrict__ bsumex,
                        int* rowptr, int* cursor, int n) {
    __shared__ int sh[256];
    int t = threadIdx.x;
    int base = blockIdx.x * 1024 + t * 4;
    int v0 = 0, v1 = 0, v2 = 0, v3 = 0;
    if (base + 0 < n) v0 = cnt[base + 0];
    if (base + 1 < n) v1 = cnt[base + 1];
    if (base + 2 < n) v2 = cnt[base + 2];
    if (base + 3 < n) v3 = cnt[base + 3];
    int s = v0 + v1 + v2 + v3;
    sh[t] = s;
    __syncthreads();
    for (int off = 1; off < 256; off <<= 1) {
        int v = (t >= off) ? sh[t - off] : 0;
        __syncthreads();
        sh[t] += v;
        __syncthreads();
    }
    int ex = (t == 0) ? 0 : sh[t - 1];
    int off0 = bsumex[blockIdx.x] + ex;
    if (base + 0 < n) { rowptr[base + 0] = off0;                cursor[base + 0] = off0; }
    if (base + 1 < n) { rowptr[base + 1] = off0 + v0;           cursor[base + 1] = off0 + v0; }
    if (base + 2 < n) { rowptr[base + 2] = off0 + v0 + v1;      cursor[base + 2] = off0 + v0 + v1; }
    if (base + 3 < n) { rowptr[base + 3] = off0 + v0 + v1 + v2; cursor[base + 3] = off0 + v0 + v1 + v2; }
}

__global__ void k_fill(const int* __restrict__ src, const int* __restrict__ dst,
                       const float* __restrict__ dis, int* cursor, int2* edges,
                       int e, int n) {
    int i = blockIdx.x * blockDim.x + threadIdx.x;
    if (i >= e + n) return;
    int s, d;
    if (i < e) { s = src[i]; d = dst[i]; }
    else       { s = d = i - e; }
    float w = dis[s] * dis[d];
    int pos = atomicAdd(&cursor[d], 1);
    edges[pos] = make_int2(s, __float_as_int(w));
}

// ----------------------------- SpMM (fp32 gather) ----------------------------
// warp per destination row, lane handles a float4 (layer 1 only)
__global__ void k_spmm(const int* __restrict__ rowptr, const int2* __restrict__ edges,
                       const float* __restrict__ xin, float* __restrict__ xout, int n) {
    int row  = (blockIdx.x * blockDim.x + threadIdx.x) >> 5;
    int lane = threadIdx.x & 31;
    if (row >= n) return;
    int s = rowptr[row], e = rowptr[row + 1];
    const float4* x4 = (const float4*)xin;
    float4 acc = make_float4(0.f, 0.f, 0.f, 0.f);
    int j = s;
    for (; j + 4 <= e; j += 4) {
        int2 e0 = __ldg(&edges[j + 0]);
        int2 e1 = __ldg(&edges[j + 1]);
        int2 e2 = __ldg(&edges[j + 2]);
        int2 e3 = __ldg(&edges[j + 3]);
        float4 v0 = __ldg(&x4[(size_t)e0.x * 32 + lane]);
        float4 v1 = __ldg(&x4[(size_t)e1.x * 32 + lane]);
        float4 v2 = __ldg(&x4[(size_t)e2.x * 32 + lane]);
        float4 v3 = __ldg(&x4[(size_t)e3.x * 32 + lane]);
        float w0 = __int_as_float(e0.y), w1 = __int_as_float(e1.y);
        float w2 = __int_as_float(e2.y), w3 = __int_as_float(e3.y);
        acc.x += w0 * v0.x; acc.y += w0 * v0.y; acc.z += w0 * v0.z; acc.w += w0 * v0.w;
        acc.x += w1 * v1.x; acc.y += w1 * v1.y; acc.z += w1 * v1.z; acc.w += w1 * v1.w;
        acc.x += w2 * v2.x; acc.y += w2 * v2.y; acc.z += w2 * v2.z; acc.w += w2 * v2.w;
        acc.x += w3 * v3.x; acc.y += w3 * v3.y; acc.z += w3 * v3.z; acc.w += w3 * v3.w;
    }
    for (; j < e; j++) {
        int2 ed = __ldg(&edges[j]);
        float w = __int_as_float(ed.y);
        float4 v = __ldg(&x4[(size_t)ed.x * 32 + lane]);
        acc.x += w * v.x; acc.y += w * v.y; acc.z += w * v.z; acc.w += w * v.w;
    }
    ((float4*)xout)[(size_t)row * 32 + lane] = acc;
}

// ----------------------------- SpMM (fp16 gather) ----------------------------
// lane handles 4 columns as uint2 (two half2); fp32 accumulate. Layers 2..L.
__global__ void k_spmm_h(const int* __restrict__ rowptr, const int2* __restrict__ edges,
                         const __half* __restrict__ xin, float* __restrict__ xout, int n) {
    int row  = (blockIdx.x * blockDim.x + threadIdx.x) >> 5;
    int lane = threadIdx.x & 31;
    if (row >= n) return;
    int s = rowptr[row], e = rowptr[row + 1];
    const uint2* xp = (const uint2*)xin;
    float4 acc = make_float4(0.f, 0.f, 0.f, 0.f);
    int j = s;
    for (; j + 4 <= e; j += 4) {
        int2 e0 = __ldg(&edges[j + 0]);
        int2 e1 = __ldg(&edges[j + 1]);
        int2 e2 = __ldg(&edges[j + 2]);
        int2 e3 = __ldg(&edges[j + 3]);
        uint2 h0 = __ldg(&xp[(size_t)e0.x * 32 + lane]);
        uint2 h1 = __ldg(&xp[(size_t)e1.x * 32 + lane]);
        uint2 h2 = __ldg(&xp[(size_t)e2.x * 32 + lane]);
        uint2 h3 = __ldg(&xp[(size_t)e3.x * 32 + lane]);
        float w0 = __int_as_float(e0.y), w1 = __int_as_float(e1.y);
        float w2 = __int_as_float(e2.y), w3 = __int_as_float(e3.y);
        float2 a, b;
        a = __half22float2(*(const __half2*)&h0.x); b = __half22float2(*(const __half2*)&h0.y);
        acc.x += w0 * a.x; acc.y += w0 * a.y; acc.z += w0 * b.x; acc.w += w0 * b.y;
        a = __half22float2(*(const __half2*)&h1.x); b = __half22float2(*(const __half2*)&h1.y);
        acc.x += w1 * a.x; acc.y += w1 * a.y; acc.z += w1 * b.x; acc.w += w1 * b.y;
        a = __half22float2(*(const __half2*)&h2.x); b = __half22float2(*(const __half2*)&h2.y);
        acc.x += w2 * a.x; acc.y += w2 * a.y; acc.z += w2 * b.x; acc.w += w2 * b.y;
        a = __half22float2(*(const __half2*)&h3.x); b = __half22float2(*(const __half2*)&h3.y);
        acc.x += w3 * a.x; acc.y += w3 * a.y; acc.z += w3 * b.x; acc.w += w3 * b.y;
    }
    for (; j < e; j++) {
        int2 ed = __ldg(&edges[j]);
        float w = __int_as_float(ed.y);
        uint2 h = __ldg(&xp[(size_t)ed.x * 32 + lane]);
        float2 a = __half22float2(*(const __half2*)&h.x);
        float2 b = __half22float2(*(const __half2*)&h.y);
        acc.x += w * a.x; acc.y += w * a.y; acc.z += w * b.x; acc.w += w * b.y;
    }
    ((float4*)xout)[(size_t)row * 32 + lane] = acc;
}

// ------------------------- tensor-core GEMM helpers --------------------------
__device__ __forceinline__ uint32_t f2tf32(float v) {
    uint32_t u;
    asm("cvt.rna.tf32.f32 %0, %1;" : "=r"(u) : "f"(v));
    return u;
}
__device__ __forceinline__ uint32_t packbf(float e0, float e1) {
    uint32_t r;
    asm("cvt.rn.bf16x2.f32 %0, %1, %2;" : "=r"(r) : "f"(e1), "f"(e0));
    return r;
}
__device__ __forceinline__ void mma8(float* c,
                                     uint32_t a0, uint32_t a1, uint32_t a2, uint32_t a3,
                                     uint32_t b0, uint32_t b1) {
    asm volatile(
        "mma.sync.aligned.m16n8k8.row.col.f32.tf32.tf32.f32 "
        "{%0,%1,%2,%3}, {%4,%5,%6,%7}, {%8,%9}, {%0,%1,%2,%3};"
        : "+f"(c[0]), "+f"(c[1]), "+f"(c[2]), "+f"(c[3])
        : "r"(a0), "r"(a1), "r"(a2), "r"(a3), "r"(b0), "r"(b1));
}

// ----------------- per-layer W fragment pre-split (ALL layers) ---------------
__global__ void k_prepw_all(const float* __restrict__ Ws, uint2* __restrict__ wh,
                            uint32_t* __restrict__ wl) {
    int l = blockIdx.x >> 5;
    int idx = (blockIdx.x & 31) * 256 + threadIdx.x;   // 0..8191
    const float* W = Ws + (size_t)l * HH * HH;
    int lane = idx & 31, tile = idx >> 5;
    int nt = tile & 15, ks = tile >> 4;
    int t = lane & 3, g = lane >> 2;
    int row = ks * 8 + t, col = nt * 8 + g;
    float v0 = W[row * HH + col];
    float v1 = W[(row + 4) * HH + col];
    uint32_t h0 = f2tf32(v0), h1 = f2tf32(v1);
    float l0 = v0 - __uint_as_float(h0), l1 = v1 - __uint_as_float(h1);
    wh[l * 8192 + idx] = make_uint2(h0, h1);
    wl[l * 8192 + idx] = packbf(l0, l1);
}

// --------------------------------- GEMM --------------------------------------
// out[m][c] = relu( sum_k A[m][k]*W[k][c] + bias[c] ) -> fp16 activations.
// Block tile 128x128, K=128. Shared holds only A fragments (96KB, 2 blocks/SM).
#define SMEM_GEMM 98304

__global__ __launch_bounds__(256)
void k_gemm_tc(const float* __restrict__ A,
               const uint2* __restrict__ wh, const uint32_t* __restrict__ wl,
               const float* __restrict__ bias, __half* __restrict__ out, int n) {
    extern __shared__ char sh[];
    uint4* Ah = (uint4*)sh;                      // 4096 slots
    uint2* Al = (uint2*)(sh + 65536);            // 4096 slots

    const int tid  = threadIdx.x;
    const int lane = tid & 31;
    const int g = lane >> 2, t = lane & 3;
    const int m0 = blockIdx.x << 7;

    // ---- stage A fragments ----
#pragma unroll
    for (int i = 0; i < 16; i++) {
        int s    = tid + i * 256;      // slot id; (s & 31) == lane
        int tile = s >> 5;             // 0..127
        int mt = tile & 7, ks = tile >> 3;
        int mrow = m0 + mt * 16 + g;
        int col  = ks * 8 + t;
        float v0 = 0.f, v1 = 0.f, v2 = 0.f, v3 = 0.f;
        if (mrow < n) {
            v0 = __ldg(&A[(size_t)mrow * HH + col]);
            v2 = __ldg(&A[(size_t)mrow * HH + col + 4]);
        }
        if (mrow + 8 < n) {
            v1 = __ldg(&A[(size_t)(mrow + 8) * HH + col]);
            v3 = __ldg(&A[(size_t)(mrow + 8) * HH + col + 4]);
        }
        uint32_t h0 = f2tf32(v0), h1 = f2tf32(v1), h2 = f2tf32(v2), h3 = f2tf32(v3);
        float l0 = v0 - __uint_as_float(h0), l1 = v1 - __uint_as_float(h1);
        float l2 = v2 - __uint_as_float(h2), l3 = v3 - __uint_as_float(h3);
        Ah[s] = make_uint4(h0, h1, h2, h3);
        Al[s] = make_uint2(packbf(l0, l1), packbf(l2, l3));
    }
    __syncthreads();

    const int warp = tid >> 5;
    const int wm = warp >> 2;      // 0..1  (64 rows each)
    const int wn = warp & 3;       // 0..3  (32 cols each)

    float acc[4][4][4];
#pragma unroll
    for (int a = 0; a < 4; a++)
#pragma unroll
        for (int b = 0; b < 4; b++)
#pragma unroll
            for (int c = 0; c < 4; c++) acc[a][b][c] = 0.f;

#pragma unroll 2
    for (int ks = 0; ks < 16; ks++) {
        uint2 bh[4]; uint32_t blp[4];
#pragma unroll
        for (int nt = 0; nt < 4; nt++) {
            int slot = (ks * 16 + wn * 4 + nt) * 32 + lane;
            bh[nt]  = __ldg(&wh[slot]);
            blp[nt] = __ldg(&wl[slot]);
        }
        uint4 ah[4]; uint2 alp[4];
#pragma unroll
        for (int mt = 0; mt < 4; mt++) {
            int slot = (ks * 8 + wm * 4 + mt) * 32 + lane;
            ah[mt]  = Ah[slot];
            alp[mt] = Al[slot];
        }
#pragma unroll
        for (int mt = 0; mt < 4; mt++) {
            uint32_t a0 = ah[mt].x, a1 = ah[mt].y, a2 = ah[mt].z, a3 = ah[mt].w;
            uint32_t q0 = alp[mt].x << 16, q1 = alp[mt].x & 0xFFFF0000u;
            uint32_t q2 = alp[mt].y << 16, q3 = alp[mt].y & 0xFFFF0000u;
#pragma unroll
            for (int nt = 0; nt < 4; nt++) {
                uint32_t b0 = bh[nt].x, b1 = bh[nt].y;
                uint32_t r0 = blp[nt] << 16, r1 = blp[nt] & 0xFFFF0000u;
                mma8(acc[mt][nt], a0, a1, a2, a3, b0, b1);   // hi*hi
                mma8(acc[mt][nt], a0, a1, a2, a3, r0, r1);   // hi*lo
                mma8(acc[mt][nt], q0, q1, q2, q3, b0, b1);   // lo*hi
            }
        }
    }

    // ---- epilogue: bias + relu + fp16 store ----
#pragma unroll
    for (int nt = 0; nt < 4; nt++) {
        int c = wn * 32 + nt * 8 + 2 * t;
        float b0 = __ldg(&bias[c]), b1 = __ldg(&bias[c + 1]);
#pragma unroll
        for (int mt = 0; mt < 4; mt++) {
            int m = m0 + wm * 64 + mt * 16 + g;
            if (m < n) {
                __half2 o = __floats2half2_rn(fmaxf(acc[mt][nt][0] + b0, 0.f),
                                              fmaxf(acc[mt][nt][1] + b1, 0.f));
                *(__half2*)&out[(size_t)m * HH + c] = o;
            }
            if (m + 8 < n) {
                __half2 o = __floats2half2_rn(fmaxf(acc[mt][nt][2] + b0, 0.f),
                                              fmaxf(acc[mt][nt][3] + b1, 0.f));
                *(__half2*)&out[(size_t)(m + 8) * HH + c] = o;
            }
        }
    }
}

// ------------------------------ pooling / head ------------------------------
// graph boundaries + zero pooled accumulator + init cnt=1 (self loop)
__global__ void k_gbz(const int* __restrict__ batch, int* gstart, float* psum,
                      int* cnt, int n, int g_num) {
    int i = blockIdx.x * blockDim.x + threadIdx.x;
    if (i < n) cnt[i] = 1;                 // self loop seed for k_count
    if (i < g_num * HH) psum[i] = 0.f;
    if (i <= g_num) {
        int lo = 0, hi = n;
        while (lo < hi) {
            int mid = (lo + hi) >> 1;
            if (batch[mid] < i) lo = mid + 1; else hi = mid;
        }
        gstart[i] = lo;
    }
}

// chunked per-graph partial sums over fp16 activations
__global__ __launch_bounds__(128)
void k_psum(const __half* __restrict__ x, const int* __restrict__ batch,
            float* __restrict__ psum, int n) {
    __shared__ int bsh[256];
    const int t = threadIdx.x;            // column 0..127
    const int r0 = blockIdx.x * 256;
    const int len = min(256, n - r0);
    for (int i = t; i < len; i += 128) bsh[i] = batch[r0 + i];
    __syncthreads();

    if (bsh[0] == bsh[len - 1]) {
        float acc = 0.f;
        int i = 0;
        for (; i + 8 <= len; i += 8) {
            float v0 = __half2float(x[(size_t)(r0 + i + 0) * HH + t]);
            float v1 = __half2float(x[(size_t)(r0 + i + 1) * HH + t]);
            float v2 = __half2float(x[(size_t)(r0 + i + 2) * HH + t]);
            float v3 = __half2float(x[(size_t)(r0 + i + 3) * HH + t]);
            float v4 = __half2float(x[(size_t)(r0 + i + 4) * HH + t]);
            float v5 = __half2float(x[(size_t)(r0 + i + 5) * HH + t]);
            float v6 = __half2float(x[(size_t)(r0 + i + 6) * HH + t]);
            float v7 = __half2float(x[(size_t)(r0 + i + 7) * HH + t]);
            acc += ((v0 + v1) + (v2 + v3)) + ((v4 + v5) + (v6 + v7));
        }
        for (; i < len; i++) acc += __half2float(x[(size_t)(r0 + i) * HH + t]);
        atomicAdd(&psum[(size_t)bsh[0] * HH + t], acc);
    } else {
        float acc = 0.f;
        int curg = bsh[0];
        for (int i = 0; i < len; i++) {
            int g = bsh[i];
            if (g != curg) { atomicAdd(&psum[(size_t)curg * HH + t], acc); acc = 0.f; curg = g; }
            acc += __half2float(x[(size_t)(r0 + i) * HH + t]);
        }
        atomicAdd(&psum[(size_t)curg * HH + t], acc);
    }
}

// head: pooled = psum/cnt ; out = pooled @ W_out + b_out
__global__ void k_out(const float* __restrict__ psum, const int* __restrict__ gstart,
                      const float* __restrict__ Wout, const float* __restrict__ bout,
                      float* __restrict__ out, int C) {
    __shared__ float pr[HH];
    int g = blockIdx.x, t = threadIdx.x;
    float cntf = (float)(gstart[g + 1] - gstart[g]);
    float inv = 1.0f / fmaxf(cntf, 1.0f);
    pr[t] = psum[(size_t)g * HH + t] * inv;
    __syncthreads();
    if (t < C) {
        float s = bout[t];
#pragma unroll 8
        for (int k = 0; k < HH; k++) s += pr[k] * Wout[k * C + t];
        out[g * C + t] = s;
    }
}

// --------------------------------- launch -----------------------------------
extern "C" void kernel_launch(void* const* d_in, const int* in_sizes, int n_in,
                              void* d_out, int out_size) {
    const float* x     = (const float*)d_in[0];
    const int*   ei    = (const int*)d_in[1];
    const int*   batch = (const int*)d_in[2];
    int iw, ibs, iwo, ibo;
    if (n_in >= 8) { iw = 4; ibs = 5; iwo = 6; ibo = 7; }  // num_graphs at index 3
    else           { iw = 3; ibs = 4; iwo = 5; ibo = 6; }
    const float* Ws   = (const float*)d_in[iw];
    const float* bs   = (const float*)d_in[ibs];
    const float* Wout = (const float*)d_in[iwo];
    const float* bout = (const float*)d_in[ibo];

    int N = in_sizes[2];
    int E = in_sizes[1] / 2;
    int H = in_sizes[0] / N;            // expect 128
    int C = in_sizes[ibo];
    int L = in_sizes[ibs] / H;
    int G = out_size / C;
    if (N > MAXN || (E + N) > MAXT || G > MAXG || H != HH || L > MAXL) return;

    void* p;
    cudaGetSymbolAddress(&p, g_cnt);     int*    cnt    = (int*)p;
    cudaGetSymbolAddress(&p, g_dis);     float*  dis    = (float*)p;
    cudaGetSymbolAddress(&p, g_rowptr);  int*    rowptr = (int*)p;
    cudaGetSymbolAddress(&p, g_cursor);  int*    cursor = (int*)p;
    cudaGetSymbolAddress(&p, g_edges);   int2*   edges  = (int2*)p;
    cudaGetSymbolAddress(&p, g_agg);     float*  agg    = (float*)p;
    cudaGetSymbolAddress(&p, g_xh1);     __half* xh1    = (__half*)p;
    cudaGetSymbolAddress(&p, g_xh2);     __half* xh2    = (__half*)p;
    cudaGetSymbolAddress(&p, g_bsum);    int*    bsum   = (int*)p;
    cudaGetSymbolAddress(&p, g_gstart);  int*    gstart = (int*)p;
    cudaGetSymbolAddress(&p, g_psum);    float*  psum   = (float*)p;
    cudaGetSymbolAddress(&p, g_wh);      uint2*  wh     = (uint2*)p;
    cudaGetSymbolAddress(&p, g_wl);      uint32_t* wl   = (uint32_t*)p;

    cudaFuncSetAttribute(k_gemm_tc, cudaFuncAttributeMaxDynamicSharedMemorySize, SMEM_GEMM);

    const int* src = ei;
    const int* dst = ei + E;

    // init cnt=1 / graph boundaries / zero pooled accumulator (one pass)
    k_gbz<<<(N + 255) / 256, 256>>>(batch, gstart, psum, cnt, N, G);
    // W fragment pre-split for all layers (off the per-layer critical path)
    k_prepw_all<<<32 * L, 256>>>(Ws, wh, wl);

    k_count<<<(E + 255) / 256, 256>>>(dst, cnt, E);

    int NB = (N + 1023) / 1024;
    k_scan1<<<NB, 256>>>(cnt, bsum, dis, N);
    k_scan2<<<1, 256>>>(bsum, rowptr, NB, N);
    k_scan3<<<NB, 256>>>(cnt, bsum, rowptr, cursor, N);
    k_fill <<<(E + N + 255) / 256, 256>>>(src, dst, dis, cursor, edges, E, N);

    const __half* xh = nullptr;
    for (int l = 0; l < L; l++) {
        if (l == 0)
            k_spmm  <<<(N + 7) / 8, 256>>>(rowptr, edges, x, agg, N);
        else
            k_spmm_h<<<(N + 7) / 8, 256>>>(rowptr, edges, xh, agg, N);
        __half* xout = (l & 1) ? xh2 : xh1;
        k_gemm_tc<<<(N + 127) / 128, 256, SMEM_GEMM>>>(agg, wh + (size_t)l * 8192,
                                                       wl + (size_t)l * 8192,
                                                       bs + (size_t)l * H, xout, N);
        xh = xout;
    }

    k_psum<<<(N + 255) / 256, 128>>>(xh, batch, psum, N);
    k_out <<<G, HH>>>(psum, gstart, Wout, bout, (float*)d_out, C);
}

// round 13
// speedup vs baseline: 2.2176x; 1.4245x over previous
#include <cuda_runtime.h>
#include <cuda_bf16.h>
#include <cuda_fp16.h>
#include <cstdint>

// ----------------------------------------------------------------------------
// GCN: 5x (GCNConv + ReLU) + global mean pool + linear head.
//   Fixed shapes: N=100000, E=1600000, H=128, C=10, L=5, G=64
//   - CSR build over dst (self-loops included), norm = dis[s]*dis[d]
//   - All activations stored fp16 (per-node quantization noise pools away).
//   - SpMM: warp-per-row fp16 gather, fp32 accumulate, fp16 agg out.
//   - GEMM: mma.m16n8k16.f16 with fp32 accumulate, TWO terms:
//       A(fp16, exact) x [W_hi(fp16) + W_lo(fp16 residual)]  -> W to 22 bits.
//     (W error is systematic -> must stay compensated; A error is random.)
//     A staged raw in 35KB smem, loaded via ldmatrix.x4.
//   - Chunked mean-pool (sorted batch) reads fp16.
// ----------------------------------------------------------------------------

#define MAXN 100352
#define MAXT 1703936      // >= E + N
#define MAXG 1024
#define MAXL 8
#define HH   128

__device__ int    g_cnt[MAXN];
__device__ float  g_dis[MAXN];
__device__ int    g_rowptr[MAXN + 1];
__device__ int    g_cursor[MAXN];
__device__ int2   g_edges[MAXT];
__device__ __half g_xh0[(size_t)MAXN * HH];   // converted input
__device__ __half g_aggh[(size_t)MAXN * HH];  // fp16 aggregate
__device__ __half g_xh1[(size_t)MAXN * HH];
__device__ __half g_xh2[(size_t)MAXN * HH];
__device__ int    g_bsum[256];
__device__ int    g_gstart[MAXG + 1];
__device__ float  g_psum[(size_t)MAXG * HH];
__device__ uint2  g_wh[MAXL * 4096];   // W fp16-hi fragments (all layers)
__device__ uint2  g_wl[MAXL * 4096];   // W fp16-residual fragments

// ------------------------------- graph prep ---------------------------------
__global__ void k_count(const int* __restrict__ dst, int* cnt, int e) {
    int i = blockIdx.x * blockDim.x + threadIdx.x;
    if (i < e) atomicAdd(&cnt[dst[i]], 1);
}

__global__ void k_scan1(const int* __restrict__ cnt, int* bsum, float* dis, int n) {
    __shared__ int sh[256];
    int t = threadIdx.x;
    int base = blockIdx.x * 1024 + t * 4;
    int s = 0;
#pragma unroll
    for (int i = 0; i < 4; i++)
        if (base + i < n) {
            int c = cnt[base + i];
            s += c;
            dis[base + i] = rsqrtf((float)c);   // cnt >= 1 always (self loop)
        }
    sh[t] = s;
    __syncthreads();
#pragma unroll
    for (int off = 128; off > 0; off >>= 1) {
        if (t < off) sh[t] += sh[t + off];
        __syncthreads();
    }
    if (t == 0) bsum[blockIdx.x] = sh[0];
}

__global__ void k_scan2(int* bsum, int* rowptr, int nb, int n) {
    __shared__ int sh[256];
    int t = threadIdx.x;
    sh[t] = (t < nb) ? bsum[t] : 0;
    __syncthreads();
    for (int off = 1; off < 256; off <<= 1) {
        int v = (t >= off) ? sh[t - off] : 0;
        __syncthreads();
        sh[t] += v;
        __syncthreads();
    }
    if (t < nb) bsum[t] = (t == 0) ? 0 : sh[t - 1];
    if (t == 0) rowptr[n] = sh[nb - 1];
}

__global__ void k_scan3(const int* __restrict__ cnt, const int* __restrict__ bsumex,
                        int* rowptr, int* cursor, int n) {
    __shared__ int sh[256];
    int t = threadIdx.x;
    int base = blockIdx.x * 1024 + t * 4;
    int v0 = 0, v1 = 0, v2 = 0, v3 = 0;
    if (base + 0 < n) v0 = cnt[base + 0];
    if (base + 1 < n) v1 = cnt[base + 1];
    if (base + 2 < n) v2 = cnt[base + 2];
    if (base + 3 < n) v3 = cnt[base + 3];
    int s = v0 + v1 + v2 + v3;
    sh[t] = s;
    __syncthreads();
    for (int off = 1; off < 256; off <<= 1) {
        int v = (t >= off) ? sh[t - off] : 0;
        __syncthreads();
        sh[t] += v;
        __syncthreads();
    }
    int ex = (t == 0) ? 0 : sh[t - 1];
    int off0 = bsumex[blockIdx.x] + ex;
    if (base + 0 < n) { rowptr[base + 0] = off0;                cursor[base + 0] = off0; }
    if (base + 1 < n) { rowptr[base + 1] = off0 + v0;           cursor[base + 1] = off0 + v0; }
    if (base + 2 < n) { rowptr[base + 2] = off0 + v0 + v1;      cursor[base + 2] = off0 + v0 + v1; }
    if (base + 3 < n) { rowptr[base + 3] = off0 + v0 + v1 + v2; cursor[base + 3] = off0 + v0 + v1 + v2; }
}

__global__ void k_fill(const int* __restrict__ src, const int* __restrict__ dst,
                       const float* __restrict__ dis, int* cursor, int2* edges,
                       int e, int n) {
    int i = blockIdx.x * blockDim.x + threadIdx.x;
    if (i >= e + n) return;
    int s, d;
    if (i < e) { s = src[i]; d = dst[i]; }
    else       { s = d = i - e; }
    float w = dis[s] * dis[d];
    int pos = atomicAdd(&cursor[d], 1);
    edges[pos] = make_int2(s, __float_as_int(w));
}

// -------------------------- input fp32 -> fp16 convert -----------------------
__global__ void k_cvt(const float* __restrict__ x, __half* __restrict__ xh, int total4) {
    int i = blockIdx.x * blockDim.x + threadIdx.x;
    if (i >= total4) return;
    float4 v = ((const float4*)x)[i];
    __half2 a = __floats2half2_rn(v.x, v.y);
    __half2 b = __floats2half2_rn(v.z, v.w);
    ((uint2*)xh)[i] = make_uint2(*(uint32_t*)&a, *(uint32_t*)&b);
}

// ----------------------------- SpMM (fp16 gather) ----------------------------
// warp per dst row; lane handles 4 columns (uint2 = two half2); fp32 accumulate;
// writes fp16 agg.
__global__ void k_spmm_h(const int* __restrict__ rowptr, const int2* __restrict__ edges,
                         const __half* __restrict__ xin, __half* __restrict__ xout, int n) {
    int row  = (blockIdx.x * blockDim.x + threadIdx.x) >> 5;
    int lane = threadIdx.x & 31;
    if (row >= n) return;
    int s = rowptr[row], e = rowptr[row + 1];
    const uint2* xp = (const uint2*)xin;
    float4 acc = make_float4(0.f, 0.f, 0.f, 0.f);
    int j = s;
    for (; j + 4 <= e; j += 4) {
        int2 e0 = __ldg(&edges[j + 0]);
        int2 e1 = __ldg(&edges[j + 1]);
        int2 e2 = __ldg(&edges[j + 2]);
        int2 e3 = __ldg(&edges[j + 3]);
        uint2 h0 = __ldg(&xp[(size_t)e0.x * 32 + lane]);
        uint2 h1 = __ldg(&xp[(size_t)e1.x * 32 + lane]);
        uint2 h2 = __ldg(&xp[(size_t)e2.x * 32 + lane]);
        uint2 h3 = __ldg(&xp[(size_t)e3.x * 32 + lane]);
        float w0 = __int_as_float(e0.y), w1 = __int_as_float(e1.y);
        float w2 = __int_as_float(e2.y), w3 = __int_as_float(e3.y);
        float2 a, b;
        a = __half22float2(*(const __half2*)&h0.x); b = __half22float2(*(const __half2*)&h0.y);
        acc.x += w0 * a.x; acc.y += w0 * a.y; acc.z += w0 * b.x; acc.w += w0 * b.y;
        a = __half22float2(*(const __half2*)&h1.x); b = __half22float2(*(const __half2*)&h1.y);
        acc.x += w1 * a.x; acc.y += w1 * a.y; acc.z += w1 * b.x; acc.w += w1 * b.y;
        a = __half22float2(*(const __half2*)&h2.x); b = __half22float2(*(const __half2*)&h2.y);
        acc.x += w2 * a.x; acc.y += w2 * a.y; acc.z += w2 * b.x; acc.w += w2 * b.y;
        a = __half22float2(*(const __half2*)&h3.x); b = __half22float2(*(const __half2*)&h3.y);
        acc.x += w3 * a.x; acc.y += w3 * a.y; acc.z += w3 * b.x; acc.w += w3 * b.y;
    }
    for (; j < e; j++) {
        int2 ed = __ldg(&edges[j]);
        float w = __int_as_float(ed.y);
        uint2 h = __ldg(&xp[(size_t)ed.x * 32 + lane]);
        float2 a = __half22float2(*(const __half2*)&h.x);
        float2 b = __half22float2(*(const __half2*)&h.y);
        acc.x += w * a.x; acc.y += w * a.y; acc.z += w * b.x; acc.w += w * b.y;
    }
    __half2 o0 = __floats2half2_rn(acc.x, acc.y);
    __half2 o1 = __floats2half2_rn(acc.z, acc.w);
    ((uint2*)xout)[(size_t)row * 32 + lane] = make_uint2(*(uint32_t*)&o0, *(uint32_t*)&o1);
}

// ------------------------- tensor-core GEMM helpers --------------------------
__device__ __forceinline__ uint32_t pack_h2(__half lo, __half hi) {
    __half2 h = __halves2half2(lo, hi);
    return *reinterpret_cast<uint32_t*>(&h);
}
__device__ __forceinline__ void mma16816(float* c,
                                         uint32_t a0, uint32_t a1, uint32_t a2, uint32_t a3,
                                         uint32_t b0, uint32_t b1) {
    asm volatile(
        "mma.sync.aligned.m16n8k16.row.col.f32.f16.f16.f32 "
        "{%0,%1,%2,%3}, {%4,%5,%6,%7}, {%8,%9}, {%0,%1,%2,%3};"
        : "+f"(c[0]), "+f"(c[1]), "+f"(c[2]), "+f"(c[3])
        : "r"(a0), "r"(a1), "r"(a2), "r"(a3), "r"(b0), "r"(b1));
}

// ----------------- per-layer W fragment pre-split (ALL layers) ---------------
// m16n8k16 B fragment: lane t holds {W[k0][n],W[k0+1][n]} and {W[k0+8][n],W[k0+9][n]}
// with n = nt*8 + t/4, k0 = ks*16 + (t%4)*2.  hi = fp16(W), lo = fp16(W - hi).
__global__ void k_prepw16(const float* __restrict__ Ws, uint2* __restrict__ wh,
                          uint2* __restrict__ wl) {
    int l = blockIdx.x >> 4;
    int idx = (blockIdx.x & 15) * 256 + threadIdx.x;   // 0..4095
    const float* W = Ws + (size_t)l * HH * HH;
    int lane = idx & 31, tile = idx >> 5;              // tile 0..127
    int nt = tile & 15, ks = tile >> 4;                // ks 0..7
    int nn = nt * 8 + (lane >> 2);
    int k0 = ks * 16 + (lane & 3) * 2;
    float v00 = W[k0 * HH + nn],       v01 = W[(k0 + 1) * HH + nn];
    float v10 = W[(k0 + 8) * HH + nn], v11 = W[(k0 + 9) * HH + nn];
    __half h00 = __float2half_rn(v00), h01 = __float2half_rn(v01);
    __half h10 = __float2half_rn(v10), h11 = __float2half_rn(v11);
    __half r00 = __float2half_rn(v00 - __half2float(h00));
    __half r01 = __float2half_rn(v01 - __half2float(h01));
    __half r10 = __float2half_rn(v10 - __half2float(h10));
    __half r11 = __float2half_rn(v11 - __half2float(h11));
    wh[l * 4096 + idx] = make_uint2(pack_h2(h00, h01), pack_h2(h10, h11));
    wl[l * 4096 + idx] = make_uint2(pack_h2(r00, r01), pack_h2(r10, r11));
}

// --------------------------------- GEMM --------------------------------------
// out[m][c] = relu( sum_k A[m][k]*W[k][c] + bias[c] ), A fp16 exact, 2-term W.
// Block tile 128x128, K=128, 8 warps. Smem: raw A tile [128][136] fp16 = 34.8KB.
#define SMEM_GEMM16 (128 * 136 * 2)

__global__ __launch_bounds__(256)
void k_gemm_f16(const __half* __restrict__ A,
                const uint2* __restrict__ wh, const uint2* __restrict__ wl,
                const float* __restrict__ bias, __half* __restrict__ out, int n) {
    extern __shared__ __half As[];                // [128][136]
    const int tid  = threadIdx.x;
    const int lane = tid & 31;
    const int warp = tid >> 5;
    const int m0 = blockIdx.x << 7;

    // ---- stage raw A tile (fp16, coalesced uint4 loads, padded smem) ----
#pragma unroll
    for (int i = 0; i < 8; i++) {
        int s   = tid + i * 256;       // 0..2047
        int row = s >> 4, cb = s & 15;
        uint4 v = make_uint4(0u, 0u, 0u, 0u);
        if (m0 + row < n)
            v = ((const uint4*)(A + (size_t)(m0 + row) * HH))[cb];
        *(uint4*)&As[row * 136 + cb * 8] = v;
    }
    __syncthreads();

    const int wm = warp >> 2;      // 0..1  (64 rows each)
    const int wn = warp & 3;       // 0..3  (32 cols each)
    const uint32_t as_base = (uint32_t)__cvta_generic_to_shared(As);

    float acc[4][4][4];
#pragma unroll
    for (int a = 0; a < 4; a++)
#pragma unroll
        for (int b = 0; b < 4; b++)
#pragma unroll
            for (int c = 0; c < 4; c++) acc[a][b][c] = 0.f;

    // ldmatrix address pattern: threads 0-15 -> rows 0-15 col 0,
    //                           threads 16-31 -> rows 0-15 col 8
    const int lrow = lane & 15;
    const int lcol = (lane >> 4) * 8;

#pragma unroll
    for (int ks = 0; ks < 8; ks++) {
        uint2 bh[4], bl[4];
#pragma unroll
        for (int nt = 0; nt < 4; nt++) {
            int slot = (ks * 16 + wn * 4 + nt) * 32 + lane;
            bh[nt] = __ldg(&wh[slot]);
            bl[nt] = __ldg(&wl[slot]);
        }
        uint32_t af[4][4];
#pragma unroll
        for (int mt = 0; mt < 4; mt++) {
            int row = wm * 64 + mt * 16 + lrow;
            int col = ks * 16 + lcol;
            uint32_t addr = as_base + (uint32_t)(row * 136 + col) * 2;
            asm volatile(
                "ldmatrix.sync.aligned.m8n8.x4.shared.b16 {%0,%1,%2,%3}, [%4];"
                : "=r"(af[mt][0]), "=r"(af[mt][1]), "=r"(af[mt][2]), "=r"(af[mt][3])
                : "r"(addr));
        }
#pragma unroll
        for (int mt = 0; mt < 4; mt++)
#pragma unroll
            for (int nt = 0; nt < 4; nt++) {
                mma16816(acc[mt][nt], af[mt][0], af[mt][1], af[mt][2], af[mt][3],
                         bh[nt].x, bh[nt].y);
                mma16816(acc[mt][nt], af[mt][0], af[mt][1], af[mt][2], af[mt][3],
                         bl[nt].x, bl[nt].y);
            }
    }

    // ---- epilogue: bias + relu + fp16 store ----
    const int g = lane >> 2, t = lane & 3;
#pragma unroll
    for (int nt = 0; nt < 4; nt++) {
        int c = wn * 32 + nt * 8 + 2 * t;
        float b0 = __ldg(&bias[c]), b1 = __ldg(&bias[c + 1]);
#pragma unroll
        for (int mt = 0; mt < 4; mt++) {
            int m = m0 + wm * 64 + mt * 16 + g;
            if (m < n) {
                __half2 o = __floats2half2_rn(fmaxf(acc[mt][nt][0] + b0, 0.f),
                                              fmaxf(acc[mt][nt][1] + b1, 0.f));
                *(__half2*)&out[(size_t)m * HH + c] = o;
            }
            if (m + 8 < n) {
                __half2 o = __floats2half2_rn(fmaxf(acc[mt][nt][2] + b0, 0.f),
                                              fmaxf(acc[mt][nt][3] + b1, 0.f));
                *(__half2*)&out[(size_t)(m + 8) * HH + c] = o;
            }
        }
    }
}

// ------------------------------ pooling / head ------------------------------
// graph boundaries + zero pooled accumulator + init cnt=1 (self loop)
__global__ void k_gbz(const int* __restrict__ batch, int* gstart, float* psum,
                      int* cnt, int n, int g_num) {
    int i = blockIdx.x * blockDim.x + threadIdx.x;
    if (i < n) cnt[i] = 1;                 // self loop seed for k_count
    if (i < g_num * HH) psum[i] = 0.f;
    if (i <= g_num) {
        int lo = 0, hi = n;
        while (lo < hi) {
            int mid = (lo + hi) >> 1;
            if (batch[mid] < i) lo = mid + 1; else hi = mid;
        }
        gstart[i] = lo;
    }
}

// chunked per-graph partial sums over fp16 activations
__global__ __launch_bounds__(128)
void k_psum(const __half* __restrict__ x, const int* __restrict__ batch,
            float* __restrict__ psum, int n) {
    __shared__ int bsh[256];
    const int t = threadIdx.x;            // column 0..127
    const int r0 = blockIdx.x * 256;
    const int len = min(256, n - r0);
    for (int i = t; i < len; i += 128) bsh[i] = batch[r0 + i];
    __syncthreads();

    if (bsh[0] == bsh[len - 1]) {
        float acc = 0.f;
        int i = 0;
        for (; i + 8 <= len; i += 8) {
            float v0 = __half2float(x[(size_t)(r0 + i + 0) * HH + t]);
            float v1 = __half2float(x[(size_t)(r0 + i + 1) * HH + t]);
            float v2 = __half2float(x[(size_t)(r0 + i + 2) * HH + t]);
            float v3 = __half2float(x[(size_t)(r0 + i + 3) * HH + t]);
            float v4 = __half2float(x[(size_t)(r0 + i + 4) * HH + t]);
            float v5 = __half2float(x[(size_t)(r0 + i + 5) * HH + t]);
            float v6 = __half2float(x[(size_t)(r0 + i + 6) * HH + t]);
            float v7 = __half2float(x[(size_t)(r0 + i + 7) * HH + t]);
            acc += ((v0 + v1) + (v2 + v3)) + ((v4 + v5) + (v6 + v7));
        }
        for (; i < len; i++) acc += __half2float(x[(size_t)(r0 + i) * HH + t]);
        atomicAdd(&psum[(size_t)bsh[0] * HH + t], acc);
    } else {
        float acc = 0.f;
        int curg = bsh[0];
        for (int i = 0; i < len; i++) {
            int g = bsh[i];
            if (g != curg) { atomicAdd(&psum[(size_t)curg * HH + t], acc); acc = 0.f; curg = g; }
            acc += __half2float(x[(size_t)(r0 + i) * HH + t]);
        }
        atomicAdd(&psum[(size_t)curg * HH + t], acc);
    }
}

// head: pooled = psum/cnt ; out = pooled @ W_out + b_out
__global__ void k_out(const float* __restrict__ psum, const int* __restrict__ gstart,
                      const float* __restrict__ Wout, const float* __restrict__ bout,
                      float* __restrict__ out, int C) {
    __shared__ float pr[HH];
    int g = blockIdx.x, t = threadIdx.x;
    float cntf = (float)(gstart[g + 1] - gstart[g]);
    float inv = 1.0f / fmaxf(cntf, 1.0f);
    pr[t] = psum[(size_t)g * HH + t] * inv;
    __syncthreads();
    if (t < C) {
        float s = bout[t];
#pragma unroll 8
        for (int k = 0; k < HH; k++) s += pr[k] * Wout[k * C + t];
        out[g * C + t] = s;
    }
}

// --------------------------------- launch -----------------------------------
extern "C" void kernel_launch(void* const* d_in, const int* in_sizes, int n_in,
                              void* d_out, int out_size) {
    const float* x     = (const float*)d_in[0];
    const int*   ei    = (const int*)d_in[1];
    const int*   batch = (const int*)d_in[2];
    int iw, ibs, iwo, ibo;
    if (n_in >= 8) { iw = 4; ibs = 5; iwo = 6; ibo = 7; }  // num_graphs at index 3
    else           { iw = 3; ibs = 4; iwo = 5; ibo = 6; }
    const float* Ws   = (const float*)d_in[iw];
    const float* bs   = (const float*)d_in[ibs];
    const float* Wout = (const float*)d_in[iwo];
    const float* bout = (const float*)d_in[ibo];

    int N = in_sizes[2];
    int E = in_sizes[1] / 2;
    int H = in_sizes[0] / N;            // expect 128
    int C = in_sizes[ibo];
    int L = in_sizes[ibs] / H;
    int G = out_size / C;
    if (N > MAXN || (E + N) > MAXT || G > MAXG || H != HH || L > MAXL) return;

    void* p;
    cudaGetSymbolAddress(&p, g_cnt);     int*    cnt    = (int*)p;
    cudaGetSymbolAddress(&p, g_dis);     float*  dis    = (float*)p;
    cudaGetSymbolAddress(&p, g_rowptr);  int*    rowptr = (int*)p;
    cudaGetSymbolAddress(&p, g_cursor);  int*    cursor = (int*)p;
    cudaGetSymbolAddress(&p, g_edges);   int2*   edges  = (int2*)p;
    cudaGetSymbolAddress(&p, g_xh0);     __half* xh0    = (__half*)p;
    cudaGetSymbolAddress(&p, g_aggh);    __half* aggh   = (__half*)p;
    cudaGetSymbolAddress(&p, g_xh1);     __half* xh1    = (__half*)p;
    cudaGetSymbolAddress(&p, g_xh2);     __half* xh2    = (__half*)p;
    cudaGetSymbolAddress(&p, g_bsum);    int*    bsum   = (int*)p;
    cudaGetSymbolAddress(&p, g_gstart);  int*    gstart = (int*)p;
    cudaGetSymbolAddress(&p, g_psum);    float*  psum   = (float*)p;
    cudaGetSymbolAddress(&p, g_wh);      uint2*  wh     = (uint2*)p;
    cudaGetSymbolAddress(&p, g_wl);      uint2*  wl     = (uint2*)p;

    cudaFuncSetAttribute(k_gemm_f16, cudaFuncAttributeMaxDynamicSharedMemorySize, SMEM_GEMM16);

    const int* src = ei;
    const int* dst = ei + E;

    // init cnt=1 / graph boundaries / zero pooled accumulator (one pass)
    k_gbz<<<(N + 255) / 256, 256>>>(batch, gstart, psum, cnt, N, G);
    // W fragment pre-split for all layers + input fp16 convert (off critical path)
    k_prepw16<<<16 * L, 256>>>(Ws, wh, wl);
    k_cvt<<<(N * (HH / 4) + 255) / 256, 256>>>(x, xh0, N * (HH / 4));

    k_count<<<(E + 255) / 256, 256>>>(dst, cnt, E);

    int NB = (N + 1023) / 1024;
    k_scan1<<<NB, 256>>>(cnt, bsum, dis, N);
    k_scan2<<<1, 256>>>(bsum, rowptr, NB, N);
    k_scan3<<<NB, 256>>>(cnt, bsum, rowptr, cursor, N);
    k_fill <<<(E + N + 255) / 256, 256>>>(src, dst, dis, cursor, edges, E, N);

    const __half* xin = xh0;
    for (int l = 0; l < L; l++) {
        k_spmm_h<<<(N + 7) / 8, 256>>>(rowptr, edges, xin, aggh, N);
        __half* xout = (l & 1) ? xh2 : xh1;
        k_gemm_f16<<<(N + 127) / 128, 256, SMEM_GEMM16>>>(aggh, wh + (size_t)l * 4096,
                                                          wl + (size_t)l * 4096,
                                                          bs + (size_t)l * H, xout, N);
        xin = xout;
    }

    k_psum<<<(N + 255) / 256, 128>>>(xin, batch, psum, N);
    k_out <<<G, HH>>>(psum, gstart, Wout, bout, (float*)d_out, C);
}